// round 15
// baseline (speedup 1.0000x reference)
#include <cuda_runtime.h>
#include <cuda_fp16.h>
#include <cstdint>
#include <cstddef>

#define B_ 16384
#define D_ 4096
#define E_ 4
#define O_ 256
#define NP 512           // pair-bucket GEMM width: 2 experts * 256, n = o*2 + which

#define BM 128
#define BN 256
#define BK 64
#define SAH 72           // smem row stride in halves (144B): conflict-free LDSM residues
#define NITER (D_/BK)    // 64
#define A_BYTES (BM * SAH * 2)           // 18432
#define B_BYTES (BN * SAH * 2)           // 36864
#define STAGE_BYTES (A_BYTES + B_BYTES)  // 55296
#define NSTAGE 3
#define THREADS 512
#define MAXMB (B_/BM + 5)   // 133
#define GEMM_CTAS (2 * MAXMB)
#define TW_BLOCKS 4096      // transpose role blocks
#define RT_BLOCKS 256       // router role blocks: 8 rows/warp, 8 warps/block
#define ROWS_PW 8

// scratch (zero-initialized at module load; GEMM self-cleans for replays)
__device__ int    g_cnt[8];                     // bucket counts
__device__ int    g_done;                       // GEMM completion counter
__device__ int    g_bidx[6 * B_];               // token id per bucket slot
__device__ float2 g_bg[6 * B_];                 // (gate_lo, gate_hi) per bucket slot
__device__ __half g_vh[(size_t)B_ * D_];        // 128 MB fp16 v
__device__ __half g_wp[(size_t)6 * NP * D_];    // 24 MB  pair-interleaved fp16 W^T

// ---------------- helpers ----------------
__device__ __forceinline__ uint32_t smem_u32(const void* p) {
    uint32_t a;
    asm("{ .reg .u64 t; cvta.to.shared.u64 t, %1; cvt.u32.u64 %0, t; }" : "=r"(a) : "l"(p));
    return a;
}
__device__ __forceinline__ uint32_t h2_bits(__half2 h) {
    uint32_t u;
    asm("mov.b32 %0, %1;" : "=r"(u) : "r"(*(uint32_t*)&h));
    return u;
}
__device__ __forceinline__ void cp16(uint32_t s, const void* g) {
    asm volatile("cp.async.cg.shared.global [%0], [%1], 16;" :: "r"(s), "l"(g));
}
#define CP_COMMIT() asm volatile("cp.async.commit_group;" ::: "memory")
#define CP_WAIT(n)  asm volatile("cp.async.wait_group %0;" :: "n"(n) : "memory")

#define LDSM4(r0, r1, r2, r3, addr) \
    asm volatile("ldmatrix.sync.aligned.m8n8.x4.shared.b16 {%0,%1,%2,%3}, [%4];" \
                 : "=r"(r0), "=r"(r1), "=r"(r2), "=r"(r3) : "r"(addr))

__device__ __forceinline__ void mma_f16(float* d, const uint32_t* a, const uint32_t* b) {
    asm volatile(
        "mma.sync.aligned.m16n8k16.row.col.f32.f16.f16.f32 "
        "{%0,%1,%2,%3}, {%4,%5,%6,%7}, {%8,%9}, {%0,%1,%2,%3};"
        : "+f"(d[0]), "+f"(d[1]), "+f"(d[2]), "+f"(d[3])
        : "r"(a[0]), "r"(a[1]), "r"(a[2]), "r"(a[3]), "r"(b[0]), "r"(b[1]));
}

// ---------------------------------------------------------------------------
// Kernel B: fused prep — router blocks FIRST (long poles scheduled early),
// transpose blocks fill in behind them.
// ---------------------------------------------------------------------------
__device__ void transpose_role(const float* __restrict__ ew, int bid) {
    __shared__ float t[32][33];
    const int e  = bid >> 10;
    const int o0 = ((bid >> 7) & 7) * 32;
    const int d0 = (bid & 127) * 32;
    const int tx = threadIdx.x & 31;
    const int ty = threadIdx.x >> 5;

    #pragma unroll
    for (int k = 0; k < 4; k++) {
        int dl = ty + 8 * k;
        t[dl][tx] = ew[((size_t)e * D_ + (d0 + dl)) * O_ + (o0 + tx)];
    }
    __syncthreads();

    const int pp[4][3] = {{0,1,2},{0,3,4},{1,3,5},{2,4,5}};
    const int ww[4][3] = {{0,0,0},{1,0,0},{1,1,0},{1,1,1}};

    const int ol = threadIdx.x >> 3;
    const int q  = threadIdx.x & 7;
    __half2 h01 = __floats2half2_rn(t[q*4+0][ol], t[q*4+1][ol]);
    __half2 h23 = __floats2half2_rn(t[q*4+2][ol], t[q*4+3][ol]);
    uint2 val = make_uint2(h2_bits(h01), h2_bits(h23));
    const int o = o0 + ol, d = d0 + q * 4;
    #pragma unroll
    for (int m = 0; m < 3; m++) {
        int pid = pp[e][m], which = ww[e][m];
        *(uint2*)&g_wp[((size_t)pid * NP + o * 2 + which) * D_ + d] = val;
    }
}

// 8 rows per warp: rw float4s loaded once per iteration and reused across
// 8 independent v streams (8x load MLP, 1/8 the rw L1 traffic).
__device__ void router_role(const float* __restrict__ v, const float* __restrict__ rw,
                            float* __restrict__ routing_out, int write_routing, int bid)
{
    int warp = (bid * 256 + (int)threadIdx.x) >> 5;   // 0..2047
    int lane = threadIdx.x & 31;
    int row0 = warp * ROWS_PW;
    if (row0 >= B_) return;

    const float4* rw4 = (const float4*)rw;
    const float4* v4[ROWS_PW];
    uint2*       vh2[ROWS_PW];
    #pragma unroll
    for (int r = 0; r < ROWS_PW; r++) {
        v4[r]  = (const float4*)(v + (size_t)(row0 + r) * D_);
        vh2[r] = (uint2*)(g_vh + (size_t)(row0 + r) * D_);
    }

    float4 acc[ROWS_PW] = {};
    #pragma unroll 1
    for (int i = lane; i < D_ / 4; i += 32) {
        float4 r0 = rw4[4 * i + 0];
        float4 r1 = rw4[4 * i + 1];
        float4 r2 = rw4[4 * i + 2];
        float4 r3 = rw4[4 * i + 3];
        #pragma unroll
        for (int r = 0; r < ROWS_PW; r++) {
            float4 vv = v4[r][i];
            acc[r].x += vv.x * r0.x + vv.y * r1.x + vv.z * r2.x + vv.w * r3.x;
            acc[r].y += vv.x * r0.y + vv.y * r1.y + vv.z * r2.y + vv.w * r3.y;
            acc[r].z += vv.x * r0.z + vv.y * r1.z + vv.z * r2.z + vv.w * r3.z;
            acc[r].w += vv.x * r0.w + vv.y * r1.w + vv.z * r2.w + vv.w * r3.w;
            __half2 h01 = __floats2half2_rn(vv.x, vv.y);
            __half2 h23 = __floats2half2_rn(vv.z, vv.w);
            vh2[r][i] = make_uint2(h2_bits(h01), h2_bits(h23));
        }
    }
    #pragma unroll
    for (int r = 0; r < ROWS_PW; r++) {
        #pragma unroll
        for (int off = 16; off; off >>= 1) {
            acc[r].x += __shfl_xor_sync(0xFFFFFFFFu, acc[r].x, off);
            acc[r].y += __shfl_xor_sync(0xFFFFFFFFu, acc[r].y, off);
            acc[r].z += __shfl_xor_sync(0xFFFFFFFFu, acc[r].z, off);
            acc[r].w += __shfl_xor_sync(0xFFFFFFFFu, acc[r].w, off);
        }
    }

    // lanes 0..7 each finish one row (all lanes hold fully-reduced sums)
    if (lane < ROWS_PW) {
        int row = row0 + lane;
        float4 a = acc[lane];
        float l[E_] = {a.x, a.y, a.z, a.w};
        float mx = fmaxf(fmaxf(l[0], l[1]), fmaxf(l[2], l[3]));
        float w[E_]; float s = 0.f;
        #pragma unroll
        for (int e = 0; e < E_; e++) { w[e] = __expf(l[e] - mx); s += w[e]; }
        float inv = 1.f / s;
        #pragma unroll
        for (int e = 0; e < E_; e++) w[e] *= inv;
        if (write_routing)
            *(float4*)&routing_out[(size_t)row * E_] = make_float4(w[0], w[1], w[2], w[3]);

        int i1 = 0;
        #pragma unroll
        for (int e = 1; e < E_; e++) if (w[e] > w[i1]) i1 = e;
        int i2 = -1;
        #pragma unroll
        for (int e = 0; e < E_; e++) {
            if (e == i1) continue;
            if (i2 < 0 || w[e] > w[i2]) i2 = e;
        }
        float gs = 1.f / (w[i1] + w[i2]);
        int lo = min(i1, i2), hi = max(i1, i2);
        float g_lo = w[lo] * gs, g_hi = w[hi] * gs;
        int pid = (lo == 0) ? (hi - 1) : ((lo == 1) ? (hi + 1) : 5);

        int slot = atomicAdd(&g_cnt[pid], 1);
        g_bidx[pid * B_ + slot] = row;
        g_bg[pid * B_ + slot] = make_float2(g_lo, g_hi);
    }
}

__global__ __launch_bounds__(256) void prep_kernel(
    const float* __restrict__ v, const float* __restrict__ rw,
    const float* __restrict__ ew,
    float* __restrict__ routing_out, int write_routing)
{
    int bid = blockIdx.x;
    if (bid < RT_BLOCKS) router_role(v, rw, routing_out, write_routing, bid);
    else                 transpose_role(ew, bid - RT_BLOCKS);
}

// ---------------------------------------------------------------------------
// Kernel C (R9-proven config): bucketed fp16 mma.sync GEMM. CTA tile
// 128x256x64, 16 warps (4m x 4n), warp tile 32x64, 3-stage cp.async,
// ONE sync per iter. Self-cleans g_cnt for the next graph replay.
// ---------------------------------------------------------------------------
__global__ __launch_bounds__(THREADS, 1) void moe_mma_kernel(float* __restrict__ out)
{
    int my = blockIdx.y;
    int pid = -1, mb = 0;
    #pragma unroll
    for (int p = 0; p < 6; p++) {
        int nb = (g_cnt[p] + BM - 1) / BM;
        if (pid < 0) {
            if (my < nb) { pid = p; mb = my; }
            else my -= nb;
        }
    }

    extern __shared__ char smraw[];
    __shared__ int s_idx[BM];
    uint32_t sb = smem_u32(smraw);

    const int tid = threadIdx.x;

    if (pid >= 0) {
        const int cnt = g_cnt[pid];
        const int m0 = mb * BM;
        const int n0 = blockIdx.x * BN;

        const int wid = tid >> 5, lane = tid & 31;
        const int warp_m = wid >> 2;        // 0..3 (32 rows)
        const int warp_n = wid & 3;         // 0..3 (64 cols)
        const int qid = lane >> 2;          // 0..7
        const int tig = lane & 3;           // 0..3

        if (tid < BM) {
            int s = m0 + tid;
            s_idx[tid] = g_bidx[pid * B_ + (s < cnt ? s : 0)];
        }
        __syncthreads();

        const int lrow = tid >> 3;          // 0..63
        const int kc = tid & 7;             // 16B chunk within row
        const __half* aptr[2];
        #pragma unroll
        for (int i = 0; i < 2; i++)
            aptr[i] = g_vh + (size_t)s_idx[lrow + i * 64] * D_ + kc * 8;
        const __half* Bsrc = g_wp + ((size_t)pid * NP + n0) * D_ + kc * 8;

        float acc[2][8][4] = {};

        #pragma unroll
        for (int st = 0; st < 2; st++) {
            int k0 = st * BK;
            uint32_t ab = sb + (uint32_t)st * STAGE_BYTES;
            uint32_t bb = ab + (uint32_t)A_BYTES;
            #pragma unroll
            for (int i = 0; i < 2; i++)
                cp16(ab + (uint32_t)((lrow + i * 64) * SAH + kc * 8) * 2u, aptr[i] + k0);
            #pragma unroll
            for (int i = 0; i < 4; i++) {
                int r = lrow + i * 64;
                cp16(bb + (uint32_t)(r * SAH + kc * 8) * 2u, Bsrc + (size_t)r * D_ + k0);
            }
            CP_COMMIT();
        }

        const int frow = (lane & 7) + 8 * ((lane >> 3) & 1);
        const int foct = lane >> 4;
        const uint32_t aoffb = (uint32_t)((warp_m * 32 + frow) * SAH * 2 + foct * 16);
        const uint32_t boffb = (uint32_t)((warp_n * 64 + frow) * SAH * 2 + foct * 16);

        #pragma unroll 1
        for (int c = 0; c < NITER; c++) {
            if (c + 1 < NITER) { CP_WAIT(1); } else { CP_WAIT(0); }
            __syncthreads();

            if (c + 2 < NITER) {
                int k0 = (c + 2) * BK;
                int st = (c + 2) % NSTAGE;
                uint32_t ab = sb + (uint32_t)st * STAGE_BYTES;
                uint32_t bb = ab + (uint32_t)A_BYTES;
                #pragma unroll
                for (int i = 0; i < 2; i++)
                    cp16(ab + (uint32_t)((lrow + i * 64) * SAH + kc * 8) * 2u, aptr[i] + k0);
                #pragma unroll
                for (int i = 0; i < 4; i++) {
                    int r = lrow + i * 64;
                    cp16(bb + (uint32_t)(r * SAH + kc * 8) * 2u, Bsrc + (size_t)r * D_ + k0);
                }
                CP_COMMIT();
            }

            uint32_t abase = sb + (uint32_t)(c % NSTAGE) * STAGE_BYTES + aoffb;
            uint32_t bbase = sb + (uint32_t)(c % NSTAGE) * STAGE_BYTES + (uint32_t)A_BYTES + boffb;

            #pragma unroll
            for (int kk = 0; kk < 4; kk++) {
                uint32_t af[2][4], bf[8][2];
                #pragma unroll
                for (int i = 0; i < 2; i++)
                    LDSM4(af[i][0], af[i][1], af[i][2], af[i][3],
                          abase + (uint32_t)(i * 16 * SAH * 2) + (uint32_t)(kk * 32));
                #pragma unroll
                for (int jp = 0; jp < 4; jp++)
                    LDSM4(bf[2*jp][0], bf[2*jp+1][0], bf[2*jp][1], bf[2*jp+1][1],
                          bbase + (uint32_t)(jp * 16 * SAH * 2) + (uint32_t)(kk * 32));
                #pragma unroll
                for (int i = 0; i < 2; i++)
                    #pragma unroll
                    for (int j = 0; j < 8; j++)
                        mma_f16(acc[i][j], af[i], bf[j]);
            }
        }

        #pragma unroll
        for (int i = 0; i < 2; i++) {
            int rA = warp_m * 32 + i * 16 + qid;
            int sAg = m0 + rA, sBg = sAg + 8;
            bool vA = sAg < cnt, vB = sBg < cnt;
            int tokA = s_idx[rA], tokB = s_idx[rA + 8];
            float2 gA = vA ? g_bg[pid * B_ + sAg] : make_float2(0.f, 0.f);
            float2 gB = vB ? g_bg[pid * B_ + sBg] : make_float2(0.f, 0.f);
            #pragma unroll
            for (int j = 0; j < 8; j++) {
                int o = (n0 + warp_n * 64 + j * 8 + tig * 2) >> 1;
                if (vA) out[(size_t)tokA * O_ + o] = gA.x * acc[i][j][0] + gA.y * acc[i][j][1];
                if (vB) out[(size_t)tokB * O_ + o] = gB.x * acc[i][j][2] + gB.y * acc[i][j][3];
            }
        }
    }

    // ---- self-clean for next graph replay: last CTA resets counters ----
    __syncthreads();
    if (tid == 0) {
        int d = atomicAdd(&g_done, 1);
        if (d == GEMM_CTAS - 1) {
            #pragma unroll
            for (int p = 0; p < 8; p++) g_cnt[p] = 0;
            g_done = 0;
        }
    }
}

// ---------------------------------------------------------------------------
extern "C" void kernel_launch(void* const* d_in, const int* in_sizes, int n_in,
                              void* d_out, int out_size) {
    const float* v  = (const float*)d_in[0];   // [16384, 4096]
    const float* rw = (const float*)d_in[1];   // [4096, 4]
    const float* ew = (const float*)d_in[2];   // [4, 4096, 256]
    float* out = (float*)d_out;

    int write_routing = (out_size >= B_ * O_ + B_ * E_) ? 1 : 0;
    float* routing = write_routing ? (out + (size_t)B_ * O_) : nullptr;

    prep_kernel<<<RT_BLOCKS + TW_BLOCKS, 256>>>(v, rw, ew, routing, write_routing);

    const int smem_bytes = NSTAGE * STAGE_BYTES;  // 162 KB
    cudaFuncSetAttribute(moe_mma_kernel, cudaFuncAttributeMaxDynamicSharedMemorySize, smem_bytes);
    moe_mma_kernel<<<dim3(NP / BN, MAXMB), THREADS, smem_bytes>>>(out);
}

// round 16
// speedup vs baseline: 1.1315x; 1.1315x over previous
#include <cuda_runtime.h>
#include <cuda_fp16.h>
#include <cstdint>
#include <cstddef>

#define B_ 16384
#define D_ 4096
#define E_ 4
#define O_ 256
#define NP 512           // pair-bucket GEMM width: 2 experts * 256, n = o*2 + which

#define BM 128
#define BN 256
#define BK 64
#define SAH 72           // smem row stride in halves (144B): conflict-free LDSM residues
#define NITER (D_/BK)    // 64
#define A_BYTES (BM * SAH * 2)           // 18432
#define B_BYTES (BN * SAH * 2)           // 36864
#define STAGE_BYTES (A_BYTES + B_BYTES)  // 55296
#define NSTAGE 3
#define THREADS 512
#define MAXMB (B_/BM + 5)   // 133
#define GEMM_CTAS (2 * MAXMB)
#define TW_BLOCKS 4096      // transpose role blocks
#define RT_BLOCKS 512       // router role blocks: 4 rows/warp, 8 warps/block
#define ROWS_PW 4

// scratch (zero-initialized at module load; GEMM self-cleans for replays)
__device__ int    g_cnt[8];                     // bucket counts
__device__ int    g_done;                       // GEMM completion counter
__device__ int    g_bidx[6 * B_];               // token id per bucket slot
__device__ float2 g_bg[6 * B_];                 // (gate_lo, gate_hi) per bucket slot
__device__ __half g_vh[(size_t)B_ * D_];        // 128 MB fp16 v
__device__ __half g_wp[(size_t)6 * NP * D_];    // 24 MB  pair-interleaved fp16 W^T

// ---------------- helpers ----------------
__device__ __forceinline__ uint32_t smem_u32(const void* p) {
    uint32_t a;
    asm("{ .reg .u64 t; cvta.to.shared.u64 t, %1; cvt.u32.u64 %0, t; }" : "=r"(a) : "l"(p));
    return a;
}
__device__ __forceinline__ uint32_t h2_bits(__half2 h) {
    uint32_t u;
    asm("mov.b32 %0, %1;" : "=r"(u) : "r"(*(uint32_t*)&h));
    return u;
}
__device__ __forceinline__ void cp16(uint32_t s, const void* g) {
    asm volatile("cp.async.cg.shared.global [%0], [%1], 16;" :: "r"(s), "l"(g));
}
#define CP_COMMIT() asm volatile("cp.async.commit_group;" ::: "memory")
#define CP_WAIT(n)  asm volatile("cp.async.wait_group %0;" :: "n"(n) : "memory")

#define LDSM4(r0, r1, r2, r3, addr) \
    asm volatile("ldmatrix.sync.aligned.m8n8.x4.shared.b16 {%0,%1,%2,%3}, [%4];" \
                 : "=r"(r0), "=r"(r1), "=r"(r2), "=r"(r3) : "r"(addr))

__device__ __forceinline__ void mma_f16(float* d, const uint32_t* a, const uint32_t* b) {
    asm volatile(
        "mma.sync.aligned.m16n8k16.row.col.f32.f16.f16.f32 "
        "{%0,%1,%2,%3}, {%4,%5,%6,%7}, {%8,%9}, {%0,%1,%2,%3};"
        : "+f"(d[0]), "+f"(d[1]), "+f"(d[2]), "+f"(d[3])
        : "r"(a[0]), "r"(a[1]), "r"(a[2]), "r"(a[3]), "r"(b[0]), "r"(b[1]));
}

// ---------------------------------------------------------------------------
// Kernel B: fused prep — router blocks FIRST (long poles scheduled early),
// transpose blocks fill in behind them. Router = 4 rows/warp (R14-proven).
// ---------------------------------------------------------------------------
__device__ void transpose_role(const float* __restrict__ ew, int bid) {
    __shared__ float t[32][33];
    const int e  = bid >> 10;
    const int o0 = ((bid >> 7) & 7) * 32;
    const int d0 = (bid & 127) * 32;
    const int tx = threadIdx.x & 31;
    const int ty = threadIdx.x >> 5;

    #pragma unroll
    for (int k = 0; k < 4; k++) {
        int dl = ty + 8 * k;
        t[dl][tx] = ew[((size_t)e * D_ + (d0 + dl)) * O_ + (o0 + tx)];
    }
    __syncthreads();

    const int pp[4][3] = {{0,1,2},{0,3,4},{1,3,5},{2,4,5}};
    const int ww[4][3] = {{0,0,0},{1,0,0},{1,1,0},{1,1,1}};

    const int ol = threadIdx.x >> 3;
    const int q  = threadIdx.x & 7;
    __half2 h01 = __floats2half2_rn(t[q*4+0][ol], t[q*4+1][ol]);
    __half2 h23 = __floats2half2_rn(t[q*4+2][ol], t[q*4+3][ol]);
    uint2 val = make_uint2(h2_bits(h01), h2_bits(h23));
    const int o = o0 + ol, d = d0 + q * 4;
    #pragma unroll
    for (int m = 0; m < 3; m++) {
        int pid = pp[e][m], which = ww[e][m];
        *(uint2*)&g_wp[((size_t)pid * NP + o * 2 + which) * D_ + d] = val;
    }
}

// 4 rows per warp: rw float4s loaded once per iteration and reused across
// 4 independent v streams (4x load MLP, 1/4 the rw L1 traffic).
__device__ void router_role(const float* __restrict__ v, const float* __restrict__ rw,
                            float* __restrict__ routing_out, int write_routing, int bid)
{
    int warp = (bid * 256 + (int)threadIdx.x) >> 5;   // 0..4095
    int lane = threadIdx.x & 31;
    int row0 = warp * ROWS_PW;
    if (row0 >= B_) return;

    const float4* rw4 = (const float4*)rw;
    const float4* v4[ROWS_PW];
    uint2*       vh2[ROWS_PW];
    #pragma unroll
    for (int r = 0; r < ROWS_PW; r++) {
        v4[r]  = (const float4*)(v + (size_t)(row0 + r) * D_);
        vh2[r] = (uint2*)(g_vh + (size_t)(row0 + r) * D_);
    }

    float4 acc[ROWS_PW] = {};
    #pragma unroll 2
    for (int i = lane; i < D_ / 4; i += 32) {
        float4 r0 = rw4[4 * i + 0];
        float4 r1 = rw4[4 * i + 1];
        float4 r2 = rw4[4 * i + 2];
        float4 r3 = rw4[4 * i + 3];
        #pragma unroll
        for (int r = 0; r < ROWS_PW; r++) {
            float4 vv = v4[r][i];
            acc[r].x += vv.x * r0.x + vv.y * r1.x + vv.z * r2.x + vv.w * r3.x;
            acc[r].y += vv.x * r0.y + vv.y * r1.y + vv.z * r2.y + vv.w * r3.y;
            acc[r].z += vv.x * r0.z + vv.y * r1.z + vv.z * r2.z + vv.w * r3.z;
            acc[r].w += vv.x * r0.w + vv.y * r1.w + vv.z * r2.w + vv.w * r3.w;
            __half2 h01 = __floats2half2_rn(vv.x, vv.y);
            __half2 h23 = __floats2half2_rn(vv.z, vv.w);
            vh2[r][i] = make_uint2(h2_bits(h01), h2_bits(h23));
        }
    }
    #pragma unroll
    for (int r = 0; r < ROWS_PW; r++) {
        #pragma unroll
        for (int off = 16; off; off >>= 1) {
            acc[r].x += __shfl_xor_sync(0xFFFFFFFFu, acc[r].x, off);
            acc[r].y += __shfl_xor_sync(0xFFFFFFFFu, acc[r].y, off);
            acc[r].z += __shfl_xor_sync(0xFFFFFFFFu, acc[r].z, off);
            acc[r].w += __shfl_xor_sync(0xFFFFFFFFu, acc[r].w, off);
        }
    }

    // lanes 0..3 each finish one row (all lanes hold fully-reduced sums)
    if (lane < ROWS_PW) {
        int row = row0 + lane;
        float4 a = acc[lane];
        float l[E_] = {a.x, a.y, a.z, a.w};
        float mx = fmaxf(fmaxf(l[0], l[1]), fmaxf(l[2], l[3]));
        float w[E_]; float s = 0.f;
        #pragma unroll
        for (int e = 0; e < E_; e++) { w[e] = __expf(l[e] - mx); s += w[e]; }
        float inv = 1.f / s;
        #pragma unroll
        for (int e = 0; e < E_; e++) w[e] *= inv;
        if (write_routing)
            *(float4*)&routing_out[(size_t)row * E_] = make_float4(w[0], w[1], w[2], w[3]);

        int i1 = 0;
        #pragma unroll
        for (int e = 1; e < E_; e++) if (w[e] > w[i1]) i1 = e;
        int i2 = -1;
        #pragma unroll
        for (int e = 0; e < E_; e++) {
            if (e == i1) continue;
            if (i2 < 0 || w[e] > w[i2]) i2 = e;
        }
        float gs = 1.f / (w[i1] + w[i2]);
        int lo = min(i1, i2), hi = max(i1, i2);
        float g_lo = w[lo] * gs, g_hi = w[hi] * gs;
        int pid = (lo == 0) ? (hi - 1) : ((lo == 1) ? (hi + 1) : 5);

        int slot = atomicAdd(&g_cnt[pid], 1);
        g_bidx[pid * B_ + slot] = row;
        g_bg[pid * B_ + slot] = make_float2(g_lo, g_hi);
    }
}

__global__ __launch_bounds__(256) void prep_kernel(
    const float* __restrict__ v, const float* __restrict__ rw,
    const float* __restrict__ ew,
    float* __restrict__ routing_out, int write_routing)
{
    int bid = blockIdx.x;
    if (bid < RT_BLOCKS) router_role(v, rw, routing_out, write_routing, bid);
    else                 transpose_role(ew, bid - RT_BLOCKS);
}

// ---------------------------------------------------------------------------
// Kernel C (R9-proven config): bucketed fp16 mma.sync GEMM. CTA tile
// 128x256x64, 16 warps (4m x 4n), warp tile 32x64, 3-stage cp.async,
// ONE sync per iter. Self-cleans g_cnt for the next graph replay.
// ---------------------------------------------------------------------------
__global__ __launch_bounds__(THREADS, 1) void moe_mma_kernel(float* __restrict__ out)
{
    int my = blockIdx.y;
    int pid = -1, mb = 0;
    #pragma unroll
    for (int p = 0; p < 6; p++) {
        int nb = (g_cnt[p] + BM - 1) / BM;
        if (pid < 0) {
            if (my < nb) { pid = p; mb = my; }
            else my -= nb;
        }
    }

    extern __shared__ char smraw[];
    __shared__ int s_idx[BM];
    uint32_t sb = smem_u32(smraw);

    const int tid = threadIdx.x;

    if (pid >= 0) {
        const int cnt = g_cnt[pid];
        const int m0 = mb * BM;
        const int n0 = blockIdx.x * BN;

        const int wid = tid >> 5, lane = tid & 31;
        const int warp_m = wid >> 2;        // 0..3 (32 rows)
        const int warp_n = wid & 3;         // 0..3 (64 cols)
        const int qid = lane >> 2;          // 0..7
        const int tig = lane & 3;           // 0..3

        if (tid < BM) {
            int s = m0 + tid;
            s_idx[tid] = g_bidx[pid * B_ + (s < cnt ? s : 0)];
        }
        __syncthreads();

        const int lrow = tid >> 3;          // 0..63
        const int kc = tid & 7;             // 16B chunk within row
        const __half* aptr[2];
        #pragma unroll
        for (int i = 0; i < 2; i++)
            aptr[i] = g_vh + (size_t)s_idx[lrow + i * 64] * D_ + kc * 8;
        const __half* Bsrc = g_wp + ((size_t)pid * NP + n0) * D_ + kc * 8;

        float acc[2][8][4] = {};

        #pragma unroll
        for (int st = 0; st < 2; st++) {
            int k0 = st * BK;
            uint32_t ab = sb + (uint32_t)st * STAGE_BYTES;
            uint32_t bb = ab + (uint32_t)A_BYTES;
            #pragma unroll
            for (int i = 0; i < 2; i++)
                cp16(ab + (uint32_t)((lrow + i * 64) * SAH + kc * 8) * 2u, aptr[i] + k0);
            #pragma unroll
            for (int i = 0; i < 4; i++) {
                int r = lrow + i * 64;
                cp16(bb + (uint32_t)(r * SAH + kc * 8) * 2u, Bsrc + (size_t)r * D_ + k0);
            }
            CP_COMMIT();
        }

        const int frow = (lane & 7) + 8 * ((lane >> 3) & 1);
        const int foct = lane >> 4;
        const uint32_t aoffb = (uint32_t)((warp_m * 32 + frow) * SAH * 2 + foct * 16);
        const uint32_t boffb = (uint32_t)((warp_n * 64 + frow) * SAH * 2 + foct * 16);

        #pragma unroll 1
        for (int c = 0; c < NITER; c++) {
            if (c + 1 < NITER) { CP_WAIT(1); } else { CP_WAIT(0); }
            __syncthreads();

            if (c + 2 < NITER) {
                int k0 = (c + 2) * BK;
                int st = (c + 2) % NSTAGE;
                uint32_t ab = sb + (uint32_t)st * STAGE_BYTES;
                uint32_t bb = ab + (uint32_t)A_BYTES;
                #pragma unroll
                for (int i = 0; i < 2; i++)
                    cp16(ab + (uint32_t)((lrow + i * 64) * SAH + kc * 8) * 2u, aptr[i] + k0);
                #pragma unroll
                for (int i = 0; i < 4; i++) {
                    int r = lrow + i * 64;
                    cp16(bb + (uint32_t)(r * SAH + kc * 8) * 2u, Bsrc + (size_t)r * D_ + k0);
                }
                CP_COMMIT();
            }

            uint32_t abase = sb + (uint32_t)(c % NSTAGE) * STAGE_BYTES + aoffb;
            uint32_t bbase = sb + (uint32_t)(c % NSTAGE) * STAGE_BYTES + (uint32_t)A_BYTES + boffb;

            #pragma unroll
            for (int kk = 0; kk < 4; kk++) {
                uint32_t af[2][4], bf[8][2];
                #pragma unroll
                for (int i = 0; i < 2; i++)
                    LDSM4(af[i][0], af[i][1], af[i][2], af[i][3],
                          abase + (uint32_t)(i * 16 * SAH * 2) + (uint32_t)(kk * 32));
                #pragma unroll
                for (int jp = 0; jp < 4; jp++)
                    LDSM4(bf[2*jp][0], bf[2*jp+1][0], bf[2*jp][1], bf[2*jp+1][1],
                          bbase + (uint32_t)(jp * 16 * SAH * 2) + (uint32_t)(kk * 32));
                #pragma unroll
                for (int i = 0; i < 2; i++)
                    #pragma unroll
                    for (int j = 0; j < 8; j++)
                        mma_f16(acc[i][j], af[i], bf[j]);
            }
        }

        #pragma unroll
        for (int i = 0; i < 2; i++) {
            int rA = warp_m * 32 + i * 16 + qid;
            int sAg = m0 + rA, sBg = sAg + 8;
            bool vA = sAg < cnt, vB = sBg < cnt;
            int tokA = s_idx[rA], tokB = s_idx[rA + 8];
            float2 gA = vA ? g_bg[pid * B_ + sAg] : make_float2(0.f, 0.f);
            float2 gB = vB ? g_bg[pid * B_ + sBg] : make_float2(0.f, 0.f);
            #pragma unroll
            for (int j = 0; j < 8; j++) {
                int o = (n0 + warp_n * 64 + j * 8 + tig * 2) >> 1;
                if (vA) out[(size_t)tokA * O_ + o] = gA.x * acc[i][j][0] + gA.y * acc[i][j][1];
                if (vB) out[(size_t)tokB * O_ + o] = gB.x * acc[i][j][2] + gB.y * acc[i][j][3];
            }
        }
    }

    // ---- self-clean for next graph replay: last CTA resets counters ----
    __syncthreads();
    if (tid == 0) {
        int d = atomicAdd(&g_done, 1);
        if (d == GEMM_CTAS - 1) {
            #pragma unroll
            for (int p = 0; p < 8; p++) g_cnt[p] = 0;
            g_done = 0;
        }
    }
}

// ---------------------------------------------------------------------------
extern "C" void kernel_launch(void* const* d_in, const int* in_sizes, int n_in,
                              void* d_out, int out_size) {
    const float* v  = (const float*)d_in[0];   // [16384, 4096]
    const float* rw = (const float*)d_in[1];   // [4096, 4]
    const float* ew = (const float*)d_in[2];   // [4, 4096, 256]
    float* out = (float*)d_out;

    int write_routing = (out_size >= B_ * O_ + B_ * E_) ? 1 : 0;
    float* routing = write_routing ? (out + (size_t)B_ * O_) : nullptr;

    prep_kernel<<<RT_BLOCKS + TW_BLOCKS, 256>>>(v, rw, ew, routing, write_routing);

    const int smem_bytes = NSTAGE * STAGE_BYTES;  // 162 KB
    cudaFuncSetAttribute(moe_mma_kernel, cudaFuncAttributeMaxDynamicSharedMemorySize, smem_bytes);
    moe_mma_kernel<<<dim3(NP / BN, MAXMB), THREADS, smem_bytes>>>(out);
}